// round 14
// baseline (speedup 1.0000x reference)
#include <cuda_runtime.h>
#include <math.h>
#include <stdint.h>

#define BB 4
#define NN 100000
#define KK 16
#define EPSF 1e-6f
#define W_CE 2.0f
#define W_DICE 0.1f

// phase A/C geometry
#define RPB 4000
#define NBLKA 25               // 25*4000 = 100000
// main kernel geometry
#define GXM 96                 // blocks per batch
#define NBLKM (GXM * BB)       // 384
#define SLICES 48              // warp-slices per bucket (96*8/16)
// epilogue layout (same as R12)
#define NE_REAL 528            // 256 D | 256 INTER | 16 S1M
#define NE_TOT (BB * NE_REAL)

__device__ unsigned char g_vlab[BB][NN];
__device__ int g_bh[BB][NBLKA][16];
__device__ int g_boff[BB][NBLKA][16];
__device__ int g_bbase[BB][16];
__device__ int g_bcnt[BB][16];
__device__ int g_list[BB][NN];
__device__ float g_sl[BB * 16 * SLICES][48];   // per-slice: 16 D | 16 B | 16 I
__device__ int g_count;

// ---------------------------------------------------------------------------
// Phase A: labels (+valid fold) + per-block histograms. Streaming shape.
// ---------------------------------------------------------------------------
__global__ void __launch_bounds__(256) phaseA_kernel(
    const float* __restrict__ gt, const float* __restrict__ valid) {
    const int b = blockIdx.y, blk = blockIdx.x;
    const int t = threadIdx.x, lane = t & 31, w = t >> 5;
    __shared__ int hist[16];
    if (t < 16) hist[t] = 0;
    __syncthreads();

    const float* gt_b = gt + (size_t)b * NN * KK;
    const float* v_b = valid + (size_t)b * NN;
    const int blkbase = blk * RPB;

    for (int wi = w; wi < RPB / 32; wi += 8) {
        const int base = blkbase + wi * 32;      // 32 rows
        float vv[16];
#pragma unroll
        for (int s = 0; s < 16; s++)
            vv[s] = __ldg(gt_b + (size_t)base * KK + s * 32 + lane);
        float myv = __ldg(v_b + base + lane);
        unsigned vb = __ballot_sync(0xffffffffu, myv > 0.5f);

        unsigned short packed = 0;
        int add0 = 255, add1 = 255;
#pragma unroll
        for (int s = 0; s < 16; s++) {
            unsigned bal = __ballot_sync(0xffffffffu, vv[s] > 0.5f);
            int lab0 = __ffs(bal & 0xffffu) - 1;
            int lab1 = __ffs(bal >> 16) - 1;
            int l0 = ((vb >> (2 * s)) & 1) ? lab0 : 255;
            int l1 = ((vb >> (2 * s + 1)) & 1) ? lab1 : 255;
            if (lane == s) {
                packed = (unsigned short)(l0 | (l1 << 8));
                add0 = l0; add1 = l1;
            }
        }
        if (lane < 16) {
            *(unsigned short*)&g_vlab[b][base + 2 * lane] = packed;
            if (add0 < 16) atomicAdd(&hist[add0], 1);
            if (add1 < 16) atomicAdd(&hist[add1], 1);
        }
    }
    __syncthreads();
    if (t < 16) g_bh[b][blk][t] = hist[t];
}

// ---------------------------------------------------------------------------
// Phase B: scan (single block) -> per-block bucket offsets + bucket bases.
// ---------------------------------------------------------------------------
__global__ void phaseB_kernel() {
    const int t = threadIdx.x;
    __shared__ int cs[BB][16];
    if (t < 64) {
        int b = t >> 4, j = t & 15;
        int run = 0;
        for (int blk = 0; blk < NBLKA; blk++) {
            g_boff[b][blk][j] = run;
            run += g_bh[b][blk][j];
        }
        cs[b][j] = run;
    }
    __syncthreads();
    if (t < 64) {
        int b = t >> 4, j = t & 15;
        int base = 0;
        for (int jj = 0; jj < j; jj++) base += cs[b][jj];
        g_bbase[b][j] = base;
        g_bcnt[b][j] = cs[b][j];
        for (int blk = 0; blk < NBLKA; blk++) g_boff[b][blk][j] += base;
    }
}

// ---------------------------------------------------------------------------
// Phase C: deterministic ranked scatter of row-ids into bucket lists.
// ---------------------------------------------------------------------------
__global__ void __launch_bounds__(256) phaseC_kernel() {
    const int b = blockIdx.y, blk = blockIdx.x;
    const int t = threadIdx.x, lane = t & 31, w = t >> 5;
    __shared__ int cnt[16];
    if (t < 16) cnt[t] = g_boff[b][blk][t];
    __syncthreads();
    const int blkbase = blk * RPB;

    for (int wave = 0; wave < 16; wave++) {
        int rloc = wave * 256 + t;
        int lab = 255;
        int rin = blkbase + rloc;
        if (rloc < RPB) lab = g_vlab[b][rin];
        for (int ws = 0; ws < 8; ws++) {
            if (w == ws) {
                unsigned mask = __match_any_sync(0xffffffffu, lab);
                if (lab < 16) {
                    int leader = __ffs(mask) - 1;
                    int rank = __popc(mask & ((1u << lane) - 1));
                    int base = 0;
                    if (lane == leader) {
                        base = cnt[lab];
                        cnt[lab] = base + __popc(mask);
                    }
                    base = __shfl_sync(mask, base, leader);
                    g_list[b][base + rank] = rin;
                }
            }
            __syncthreads();
        }
    }
}

// ---------------------------------------------------------------------------
// Main kernel: per-warp bucket-slice PRODUCTS (no per-element logs).
// Lane: i = lane&15 (mask column), rh = lane>>4 (row parity within iter).
// ---------------------------------------------------------------------------
__global__ void __launch_bounds__(256) main_kernel(
    const float* __restrict__ mask, float* __restrict__ out) {
    __shared__ float facc[NE_TOT];
    __shared__ float tmpB[BB][16][16];   // [b][j][i] = sum_s Bslice
    __shared__ float cost[BB][KK][KK];
    __shared__ float mS1M[BB][KK], mSUMM[BB][KK], mSUMG[BB][KK], mV[BB];
    __shared__ int colmap[BB][KK];
    __shared__ float rce[BB * KK], rdice[BB * KK];
    __shared__ int is_last;

    const int b = blockIdx.y, bx = blockIdx.x;
    const int t = threadIdx.x, lane = t & 31, w = t >> 5;
    const int i = lane & 15, rh = lane >> 4;
    const unsigned FULL = 0xffffffffu;
    const int gw = bx * 8 + w;          // [0, 768)
    const int j = gw / SLICES;          // bucket
    const int s = gw % SLICES;          // slice

    const float* mask_b = mask + (size_t)b * NN * KK;
    const int cntb = g_bcnt[b][j];
    const int baseb = g_bbase[b][j];
    const int chunk = (cntb + SLICES - 1) / SLICES;
    int lo = s * chunk; if (lo > cntb) lo = cntb;
    int hi = lo + chunk; if (hi > cntb) hi = cntb;
    const int* lst = &g_list[b][0] + baseb;

    float Pm = 1.0f, P1 = 1.0f, I = 0.0f;
    int Em = 0, E1 = 0;

    const int n4 = lo + ((hi - lo) & ~3);
    for (int it = lo; it < n4; it += 4) {
        int id0 = __ldg(lst + it), id1 = __ldg(lst + it + 1);
        int id2 = __ldg(lst + it + 2), id3 = __ldg(lst + it + 3);
        int rA = rh ? id1 : id0;
        int rB = rh ? id3 : id2;
        float mA = __ldg(mask_b + (size_t)rA * 16 + i);
        float mB = __ldg(mask_b + (size_t)rB * 16 + i);

        Pm *= mA; P1 *= (1.0f - mA); I += mA;
        Pm *= mB; P1 *= (1.0f - mB); I += mB;

        int bm = __float_as_int(Pm);
        Em += (bm >> 23) - 127;
        Pm = __int_as_float((bm & 0x7fffff) | 0x3f800000);
        int b1 = __float_as_int(P1);
        E1 += (b1 >> 23) - 127;
        P1 = __int_as_float((b1 & 0x7fffff) | 0x3f800000);
    }
    for (int it = n4; it < hi; it++) {
        int id = __ldg(lst + it);
        float m = __ldg(mask_b + (size_t)id * 16 + i);
        float mm = rh ? 1.0f : m;
        float uu = rh ? 1.0f : (1.0f - m);
        Pm *= mm; P1 *= uu; I += rh ? 0.0f : m;
        int bm = __float_as_int(Pm);
        Em += (bm >> 23) - 127;
        Pm = __int_as_float((bm & 0x7fffff) | 0x3f800000);
        int b1 = __float_as_int(P1);
        E1 += (b1 >> 23) - 127;
        P1 = __int_as_float((b1 & 0x7fffff) | 0x3f800000);
    }

    // combine rh halves (products multiply, exponents add, INTER adds)
    Pm *= __shfl_xor_sync(FULL, Pm, 16);
    Em += __shfl_xor_sync(FULL, Em, 16);
    P1 *= __shfl_xor_sync(FULL, P1, 16);
    E1 += __shfl_xor_sync(FULL, E1, 16);
    I += __shfl_xor_sync(FULL, I, 16);

    float logm = (float)Em + __log2f(Pm);   // sum log2(m) over slice rows
    float log1 = (float)E1 + __log2f(P1);   // sum log2(1-m)
    float* slot = g_sl[(b * 16 + j) * SLICES + s];
    if (lane < 16) {
        slot[i] = log1 - logm;   // D slice
        slot[16 + i] = log1;     // B slice (for S1M)
        slot[32 + i] = I;        // INTER slice
    }

    __threadfence();
    __syncthreads();
    if (t == 0) {
        int old = atomicAdd(&g_count, 1);
        is_last = (old == NBLKM - 1);
    }
    __syncthreads();
    if (!is_last) return;
    if (t == 0) g_count = 0;

    // ---- reduce slices: 3072 outputs = 12 per thread ----
    {
        float acc[12];
#pragma unroll
        for (int k = 0; k < 12; k++) acc[k] = 0.0f;
        for (int ss = 0; ss < SLICES; ss++) {
#pragma unroll
            for (int k = 0; k < 12; k++) {
                int q = t + k * 256;                 // [0, 3072)
                int kind = q >> 10;                  // 0:D 1:B 2:I
                int sub = q & 1023;
                int bb2 = sub >> 8;
                int jj = (sub >> 4) & 15;
                int ii = sub & 15;
                acc[k] += g_sl[(bb2 * 16 + jj) * SLICES + ss][kind * 16 + ii];
            }
        }
#pragma unroll
        for (int k = 0; k < 12; k++) {
            int q = t + k * 256;
            int kind = q >> 10;
            int sub = q & 1023;
            int bb2 = sub >> 8;
            int jj = (sub >> 4) & 15;
            int ii = sub & 15;
            if (kind == 0) facc[bb2 * NE_REAL + ii * 16 + jj] = acc[k];
            else if (kind == 2) facc[bb2 * NE_REAL + 256 + ii * 16 + jj] = acc[k];
            else tmpB[bb2][jj][ii] = acc[k];
        }
    }
    __syncthreads();
    if (t < 64) {
        int bb2 = t >> 4, ii = t & 15;
        float sm = 0.0f;
#pragma unroll
        for (int jj = 0; jj < 16; jj++) sm += tmpB[bb2][jj][ii];
        facc[bb2 * NE_REAL + 512 + ii] = -sm;   // S1M = -sum log2(1-m)
    }
    __syncthreads();

    // ---- marginals from INTER (+ direct S1M) ----
    if (t < BB * KK) {
        int bb2 = t / KK, q = t % KK;
        const float* F = facc + bb2 * NE_REAL;
        float summ = 0.0f, sumg = 0.0f;
#pragma unroll
        for (int x = 0; x < KK; x++) {
            summ += F[256 + q * 16 + x];
            sumg += F[256 + x * 16 + q];
        }
        mS1M[bb2][q] = F[512 + q];
        mSUMM[bb2][q] = summ;
        mSUMG[bb2][q] = sumg;
    }
    __syncthreads();
    if (t < BB) {
        float v = 0.0f;
#pragma unroll
        for (int x = 0; x < KK; x++) v += mSUMG[t][x];
        mV[t] = v;
    }
    __syncthreads();

    // ---- cost matrices ----
    const float LN2 = 0.69314718055994530942f;
    for (int idx = t; idx < BB * 256; idx += 256) {
        int bb2 = idx >> 8;
        int r = idx & 255;
        int ii = r >> 4, jj = r & 15;
        const float* F = facc + bb2 * NE_REAL;
        float denom = fmaxf(mV[bb2], 1.0f);
        float ce = LN2 * (F[ii * 16 + jj] + mS1M[bb2][ii]) / denom;
        float dice = 1.0f - 2.0f * F[256 + ii * 16 + jj] /
                                (mSUMM[bb2][ii] + mSUMG[bb2][jj] + EPSF);
        cost[bb2][ii][jj] = W_CE * ce + W_DICE * dice;
    }
    __syncthreads();

    // ---- warp-parallel Hungarian (JV), one warp per batch ----
    if (w < BB) {
        const int bb2 = w;
        float ur = 0.0f, vv = 0.0f;
        int pcol = 0;
        for (int ii = 1; ii <= KK; ii++) {
            if (lane == 0) pcol = ii;
            float minv = 1e30f;
            int way = 0, used = 0, rowcov = 0, j0 = 0;
            while (true) {
                if (lane == j0) used = 1;
                int i0 = __shfl_sync(FULL, pcol, j0);
                if (lane == i0) rowcov = 1;
                float u_i0 = __shfl_sync(FULL, ur, i0);
                int active = (lane >= 1 && lane <= KK && !used);
                if (active) {
                    float c = cost[bb2][i0 - 1][lane - 1];
                    float cur = c - u_i0 - vv;
                    if (cur < minv) { minv = cur; way = j0; }
                }
                float val = active ? minv : 1e30f;
                float red = val;
#pragma unroll
                for (int off = 16; off; off >>= 1)
                    red = fminf(red, __shfl_xor_sync(FULL, red, off));
                unsigned bal = __ballot_sync(FULL, val == red);
                int j1 = __ffs(bal) - 1;
                float delta = red;
                if (rowcov) ur += delta;
                if (used) vv -= delta;
                else if (lane >= 1 && lane <= KK) minv -= delta;
                j0 = j1;
                int pj = __shfl_sync(FULL, pcol, j0);
                if (pj == 0) break;
            }
            while (j0 != 0) {
                int j1 = __shfl_sync(FULL, way, j0);
                int pv = __shfl_sync(FULL, pcol, j1);
                if (lane == j0) pcol = pv;
                j0 = j1;
            }
        }
        if (lane >= 1 && lane <= KK) colmap[bb2][pcol - 1] = lane - 1;
    }
    __syncthreads();

    // ---- loss ----
    if (t < BB * KK) {
        int bb2 = t / KK, ii = t % KK;
        int jj = colmap[bb2][ii];
        const float* F = facc + bb2 * NE_REAL;
        rce[t] = LN2 * (F[ii * 16 + jj] + mS1M[bb2][ii]);
        rdice[t] = 1.0f - 2.0f * F[256 + ii * 16 + jj] /
                              (mSUMM[bb2][ii] + mSUMG[bb2][jj] + EPSF);
    }
    __syncthreads();

    if (t == 0) {
        float cs = 0.0f, ds = 0.0f, vt = 0.0f;
        for (int x = 0; x < BB * KK; x++) { cs += rce[x]; ds += rdice[x]; }
        for (int bb2 = 0; bb2 < BB; bb2++) vt += mV[bb2];
        float l_ce = cs / (fmaxf(vt, 1.0f) * (float)KK);
        float l_dice = ds / (float)(BB * KK);
        out[0] = W_CE * l_ce + W_DICE * l_dice;
    }
}

// ---------------------------------------------------------------------------
extern "C" void kernel_launch(void* const* d_in, const int* in_sizes, int n_in,
                              void* d_out, int out_size) {
    const float* mask = (const float*)d_in[0];
    const float* gt = (const float*)d_in[1];
    const float* valid = (const float*)d_in[2];
    float* out = (float*)d_out;

    dim3 gA(NBLKA, BB);
    phaseA_kernel<<<gA, 256>>>(gt, valid);
    phaseB_kernel<<<1, 64>>>();
    phaseC_kernel<<<gA, 256>>>();
    dim3 gM(GXM, BB);
    main_kernel<<<gM, 256>>>(mask, out);
}

// round 15
// speedup vs baseline: 1.8191x; 1.8191x over previous
#include <cuda_runtime.h>
#include <math.h>
#include <stdint.h>

#define BB 4
#define NN 100000
#define KK 16
#define EPSF 1e-6f
#define W_CE 2.0f
#define W_DICE 0.1f

#define CHK 256                        // rows per chunk (one warp in A/C)
#define NCHK 391                       // 390*256 + 160 = 100000 (160 = 5*32)
#define GAB 49                         // ceil(391/8) blocks per batch (A, C)
#define SLICES 32                      // warp-slices per bucket in MAIN
#define GXM 64                         // MAIN blocks per batch (64*8 = 512 = 16*32)
#define NBLKM (GXM * BB)               // 256
#define NE_REAL 528                    // 256 D | 256 INTER | 16 S1M
#define NE_TOT (BB * NE_REAL)

__device__ unsigned char g_vlab[BB][NN];
__device__ int g_hist[BB][NCHK][16];
__device__ int g_off[BB][NCHK][16];    // within-bucket exclusive offsets
__device__ int g_bcnt[BB][16];
__device__ float g_msort[BB][NN * 16]; // bucket-sorted valid mask rows
__device__ float g_sl[BB * 16 * SLICES][48];  // per-slice: 16 D | 16 B | 16 I
__device__ int g_count;                // self-resetting

// ---------------------------------------------------------------------------
// Phase A: labels (valid-folded) + per-chunk histograms. Streaming shape.
// ---------------------------------------------------------------------------
__global__ void __launch_bounds__(256) phaseA_kernel(
    const float* __restrict__ gt, const float* __restrict__ valid) {
    const int b = blockIdx.y;
    const int t = threadIdx.x, lane = t & 31, w = t >> 5;
    const int c = blockIdx.x * 8 + w;
    __shared__ int hist_s[8][16];
    if (lane < 16) hist_s[w][lane] = 0;
    if (c >= NCHK) return;

    const float* gt_b = gt + (size_t)b * NN * KK;
    const float* v_b = valid + (size_t)b * NN;
    const int c0 = c * CHK;
    const int nrows = (c == NCHK - 1) ? (NN - c0) : CHK;   // 256 or 160
    const int iters = nrows >> 5;
    const unsigned FULL = 0xffffffffu;

    for (int it = 0; it < iters; it++) {
        const int base = c0 + it * 32;
        const float* src = gt_b + (size_t)base * KK;
        float vv[16];
#pragma unroll
        for (int s = 0; s < 16; s++) vv[s] = __ldg(src + s * 32 + lane);
        float myv = __ldg(v_b + base + lane);

        int mylab = 255;
#pragma unroll
        for (int s = 0; s < 16; s++) {
            unsigned bal = __ballot_sync(FULL, vv[s] > 0.5f);
            int l0 = __ffs(bal & 0xffffu) - 1;
            int l1 = __ffs(bal >> 16) - 1;
            if ((lane >> 1) == s) mylab = (lane & 1) ? l1 : l0;
        }
        if (myv <= 0.5f) mylab = 255;
        g_vlab[b][base + lane] = (unsigned char)mylab;

        unsigned mg = __match_any_sync(FULL, mylab);
        if (mylab < 16) {
            int leader = __ffs(mg) - 1;
            if (lane == leader) hist_s[w][mylab] += __popc(mg);
        }
    }
    __syncwarp();
    if (lane < 16) g_hist[b][c][lane] = hist_s[w][lane];
}

// ---------------------------------------------------------------------------
// Phase B: parallel within-bucket scans. One block per (b, j), 512 threads.
// ---------------------------------------------------------------------------
__global__ void __launch_bounds__(512) phaseB_kernel() {
    const int b = blockIdx.x >> 4, j = blockIdx.x & 15;
    const int t = threadIdx.x;
    __shared__ int sc[512];
    int o = (t < NCHK) ? g_hist[b][t][j] : 0;
    sc[t] = o;
    __syncthreads();
    for (int off = 1; off < 512; off <<= 1) {
        int v = (t >= off) ? sc[t - off] : 0;
        __syncthreads();
        sc[t] += v;
        __syncthreads();
    }
    if (t < NCHK) g_off[b][t][j] = sc[t] - o;   // exclusive
    if (t == NCHK - 1) g_bcnt[b][j] = sc[t];
}

// ---------------------------------------------------------------------------
// Phase C: scatter mask rows into bucket-sorted g_msort. Sequential reads,
// 64B-row scattered writes.
// ---------------------------------------------------------------------------
__global__ void __launch_bounds__(256) phaseC_kernel(
    const float* __restrict__ mask) {
    const int b = blockIdx.y;
    const int t = threadIdx.x, lane = t & 31, w = t >> 5;
    const int c = blockIdx.x * 8 + w;
    __shared__ int off_s[8][16];
    if (c >= NCHK) return;
    const unsigned FULL = 0xffffffffu;

    // per-warp bucket bases: bbase[j] = sum_{j'<j} cnt[j']
    {
        int cnt = (lane < 16) ? g_bcnt[b][lane] : 0;
        int inc = cnt;
#pragma unroll
        for (int d = 1; d < 16; d <<= 1) {
            int v = __shfl_up_sync(FULL, inc, d);
            if (lane >= d && lane < 16) inc += v;
        }
        if (lane < 16) off_s[w][lane] = g_off[b][c][lane] + (inc - cnt);
    }
    __syncwarp();

    const float* mask_b = mask + (size_t)b * NN * KK;
    float* dst_b = g_msort[b];
    const int c0 = c * CHK;
    const int nrows = (c == NCHK - 1) ? (NN - c0) : CHK;
    const int iters = nrows >> 5;
    const int i = lane & 15, rh = lane >> 4;

    for (int it = 0; it < iters; it++) {
        const int base = c0 + it * 32;
        const float* src = mask_b + (size_t)base * KK;
        float vv[16];
#pragma unroll
        for (int s = 0; s < 16; s++) vv[s] = __ldg(src + s * 32 + lane);

        int mylab = g_vlab[b][base + lane];
        unsigned mg = __match_any_sync(FULL, mylab);
        int idx = -1;
        if (mylab < 16) {
            int leader = __ffs(mg) - 1;
            int rank = __popc(mg & ((1u << lane) - 1));
            int bs = 0;
            if (lane == leader) {
                bs = off_s[w][mylab];
                off_s[w][mylab] = bs + __popc(mg);
            }
            bs = __shfl_sync(mg, bs, leader);
            idx = bs + rank;
        }
#pragma unroll
        for (int s = 0; s < 16; s++) {
            int d = __shfl_sync(FULL, idx, 2 * s + rh);
            if (d >= 0) dst_b[(size_t)d * 16 + i] = vv[s];
        }
    }
}

// ---------------------------------------------------------------------------
// MAIN: sequential product-accumulation over bucket slices + full epilogue.
// ---------------------------------------------------------------------------
__global__ void __launch_bounds__(256) main_kernel(float* __restrict__ out) {
    __shared__ float facc[NE_TOT];
    __shared__ float tmpB[BB][16][16];
    __shared__ float cost[BB][KK][KK];
    __shared__ float mS1M[BB][KK], mSUMM[BB][KK], mSUMG[BB][KK], mV[BB];
    __shared__ int colmap[BB][KK];
    __shared__ float rce[BB * KK], rdice[BB * KK];
    __shared__ int is_last;

    const int b = blockIdx.y, bx = blockIdx.x;
    const int t = threadIdx.x, lane = t & 31, w = t >> 5;
    const unsigned FULL = 0xffffffffu;
    const int gw = bx * 8 + w;          // [0, 512)
    const int j = gw >> 5;              // bucket
    const int s = gw & 31;              // slice

    // bucket base/count via lane scan
    int cnt16 = (lane < 16) ? g_bcnt[b][lane] : 0;
    int inc = cnt16;
#pragma unroll
    for (int d = 1; d < 16; d <<= 1) {
        int v = __shfl_up_sync(FULL, inc, d);
        if (lane >= d && lane < 16) inc += v;
    }
    const int cj = __shfl_sync(FULL, cnt16, j);
    const int bbase = __shfl_sync(FULL, inc, j) - cj;
    const int chunk = (cj + SLICES - 1) / SLICES;
    int lo = s * chunk; if (lo > cj) lo = cj;
    int hi = lo + chunk; if (hi > cj) hi = cj;

    const float* src = g_msort[b] + (size_t)(bbase + lo) * 16;
    const int nrows = hi - lo;
    const int rh = lane >> 4;

    float Pm = 1.0f, P1 = 1.0f, I = 0.0f;
    int Em = 0, E1 = 0;

#define RENORM()                                                             \
    do {                                                                     \
        int bm = __float_as_int(Pm);                                         \
        Em += (bm >> 23) - 127;                                              \
        Pm = __int_as_float((bm & 0x7fffff) | 0x3f800000);                   \
        int b1 = __float_as_int(P1);                                         \
        E1 += (b1 >> 23) - 127;                                              \
        P1 = __int_as_float((b1 & 0x7fffff) | 0x3f800000);                   \
    } while (0)

    int g = 0;
    for (; g + 32 <= nrows; g += 32) {
        float vv[16];
#pragma unroll
        for (int s2 = 0; s2 < 16; s2++)
            vv[s2] = __ldg(src + (size_t)g * 16 + s2 * 32 + lane);
#pragma unroll
        for (int s2 = 0; s2 < 16; s2++) {
            float m = vv[s2];
            Pm *= m; P1 *= (1.0f - m); I += m;
            if ((s2 & 3) == 3) RENORM();
        }
    }
    if (g < nrows) {   // tail group
        const int rem = nrows - g;
#pragma unroll
        for (int s2 = 0; s2 < 16; s2++) {
            int r2 = 2 * s2 + rh;
            int ok = (r2 < rem);
            float m = ok ? __ldg(src + (size_t)g * 16 + s2 * 32 + lane) : 0.5f;
            float fm = ok ? m : 1.0f;
            float f1 = ok ? (1.0f - m) : 1.0f;
            Pm *= fm; P1 *= f1; I += ok ? m : 0.0f;
            if ((s2 & 3) == 3) RENORM();
        }
    }
    RENORM();

    // combine rh halves
    Pm *= __shfl_xor_sync(FULL, Pm, 16);
    Em += __shfl_xor_sync(FULL, Em, 16);
    P1 *= __shfl_xor_sync(FULL, P1, 16);
    E1 += __shfl_xor_sync(FULL, E1, 16);
    I += __shfl_xor_sync(FULL, I, 16);

    float logm = (float)Em + __log2f(Pm);
    float log1 = (float)E1 + __log2f(P1);
    float* slot = g_sl[(b * 16 + j) * SLICES + s];
    if (lane < 16) {
        slot[lane] = log1 - logm;   // D slice
        slot[16 + lane] = log1;     // B slice (for S1M)
        slot[32 + lane] = I;        // INTER slice
    }

    __threadfence();
    __syncthreads();
    if (t == 0) {
        int old = atomicAdd(&g_count, 1);
        is_last = (old == NBLKM - 1);
    }
    __syncthreads();
    if (!is_last) return;
    if (t == 0) g_count = 0;

    // ---- reduce slices: 3072 outputs = 12 per thread ----
    {
        float acc[12];
#pragma unroll
        for (int k = 0; k < 12; k++) acc[k] = 0.0f;
        for (int ss = 0; ss < SLICES; ss++) {
#pragma unroll
            for (int k = 0; k < 12; k++) {
                int q = t + k * 256;
                int kind = q >> 10;
                int sub = q & 1023;
                int bb2 = sub >> 8;
                int jj = (sub >> 4) & 15;
                int ii = sub & 15;
                acc[k] += g_sl[(bb2 * 16 + jj) * SLICES + ss][kind * 16 + ii];
            }
        }
#pragma unroll
        for (int k = 0; k < 12; k++) {
            int q = t + k * 256;
            int kind = q >> 10;
            int sub = q & 1023;
            int bb2 = sub >> 8;
            int jj = (sub >> 4) & 15;
            int ii = sub & 15;
            if (kind == 0) facc[bb2 * NE_REAL + ii * 16 + jj] = acc[k];
            else if (kind == 2) facc[bb2 * NE_REAL + 256 + ii * 16 + jj] = acc[k];
            else tmpB[bb2][jj][ii] = acc[k];
        }
    }
    __syncthreads();
    if (t < 64) {
        int bb2 = t >> 4, ii = t & 15;
        float sm = 0.0f;
#pragma unroll
        for (int jj = 0; jj < 16; jj++) sm += tmpB[bb2][jj][ii];
        facc[bb2 * NE_REAL + 512 + ii] = -sm;   // S1M
    }
    __syncthreads();

    // ---- marginals ----
    if (t < BB * KK) {
        int bb2 = t / KK, q = t % KK;
        const float* F = facc + bb2 * NE_REAL;
        float summ = 0.0f, sumg = 0.0f;
#pragma unroll
        for (int x = 0; x < KK; x++) {
            summ += F[256 + q * 16 + x];
            sumg += F[256 + x * 16 + q];
        }
        mS1M[bb2][q] = F[512 + q];
        mSUMM[bb2][q] = summ;
        mSUMG[bb2][q] = sumg;
    }
    __syncthreads();
    if (t < BB) {
        float v = 0.0f;
#pragma unroll
        for (int x = 0; x < KK; x++) v += (float)g_bcnt[t][x];
        mV[t] = v;
    }
    __syncthreads();

    // ---- cost matrices ----
    const float LN2 = 0.69314718055994530942f;
    for (int idx = t; idx < BB * 256; idx += 256) {
        int bb2 = idx >> 8;
        int r = idx & 255;
        int ii = r >> 4, jj = r & 15;
        const float* F = facc + bb2 * NE_REAL;
        float denom = fmaxf(mV[bb2], 1.0f);
        float ce = LN2 * (F[ii * 16 + jj] + mS1M[bb2][ii]) / denom;
        float dice = 1.0f - 2.0f * F[256 + ii * 16 + jj] /
                                (mSUMM[bb2][ii] + mSUMG[bb2][jj] + EPSF);
        cost[bb2][ii][jj] = W_CE * ce + W_DICE * dice;
    }
    __syncthreads();

    // ---- warp-parallel Hungarian (JV), one warp per batch ----
    if (w < BB) {
        const int bb2 = w;
        float ur = 0.0f, vv = 0.0f;
        int pcol = 0;
        for (int ii = 1; ii <= KK; ii++) {
            if (lane == 0) pcol = ii;
            float minv = 1e30f;
            int way = 0, used = 0, rowcov = 0, j0 = 0;
            while (true) {
                if (lane == j0) used = 1;
                int i0 = __shfl_sync(FULL, pcol, j0);
                if (lane == i0) rowcov = 1;
                float u_i0 = __shfl_sync(FULL, ur, i0);
                int active = (lane >= 1 && lane <= KK && !used);
                if (active) {
                    float c2 = cost[bb2][i0 - 1][lane - 1];
                    float cur = c2 - u_i0 - vv;
                    if (cur < minv) { minv = cur; way = j0; }
                }
                float val = active ? minv : 1e30f;
                float red = val;
#pragma unroll
                for (int off = 16; off; off >>= 1)
                    red = fminf(red, __shfl_xor_sync(FULL, red, off));
                unsigned bal = __ballot_sync(FULL, val == red);
                int j1 = __ffs(bal) - 1;
                float delta = red;
                if (rowcov) ur += delta;
                if (used) vv -= delta;
                else if (lane >= 1 && lane <= KK) minv -= delta;
                j0 = j1;
                int pj = __shfl_sync(FULL, pcol, j0);
                if (pj == 0) break;
            }
            while (j0 != 0) {
                int j1 = __shfl_sync(FULL, way, j0);
                int pv = __shfl_sync(FULL, pcol, j1);
                if (lane == j0) pcol = pv;
                j0 = j1;
            }
        }
        if (lane >= 1 && lane <= KK) colmap[bb2][pcol - 1] = lane - 1;
    }
    __syncthreads();

    // ---- loss ----
    if (t < BB * KK) {
        int bb2 = t / KK, ii = t % KK;
        int jj = colmap[bb2][ii];
        const float* F = facc + bb2 * NE_REAL;
        rce[t] = LN2 * (F[ii * 16 + jj] + mS1M[bb2][ii]);
        rdice[t] = 1.0f - 2.0f * F[256 + ii * 16 + jj] /
                              (mSUMM[bb2][ii] + mSUMG[bb2][jj] + EPSF);
    }
    __syncthreads();

    if (t == 0) {
        float cs = 0.0f, ds = 0.0f, vt = 0.0f;
        for (int x = 0; x < BB * KK; x++) { cs += rce[x]; ds += rdice[x]; }
        for (int bb2 = 0; bb2 < BB; bb2++) vt += mV[bb2];
        float l_ce = cs / (fmaxf(vt, 1.0f) * (float)KK);
        float l_dice = ds / (float)(BB * KK);
        out[0] = W_CE * l_ce + W_DICE * l_dice;
    }
}

// ---------------------------------------------------------------------------
extern "C" void kernel_launch(void* const* d_in, const int* in_sizes, int n_in,
                              void* d_out, int out_size) {
    const float* mask = (const float*)d_in[0];
    const float* gt = (const float*)d_in[1];
    const float* valid = (const float*)d_in[2];
    float* out = (float*)d_out;

    dim3 gA(GAB, BB);
    phaseA_kernel<<<gA, 256>>>(gt, valid);
    phaseB_kernel<<<64, 512>>>();
    phaseC_kernel<<<gA, 256>>>(mask);
    dim3 gM(GXM, BB);
    main_kernel<<<gM, 256>>>(out);
}

// round 16
// speedup vs baseline: 2.0987x; 1.1537x over previous
#include <cuda_runtime.h>
#include <math.h>
#include <stdint.h>

#define BB 4
#define NN 100000
#define KK 16
#define EPSF 1e-6f
#define W_CE 2.0f
#define W_DICE 0.1f

#define CHK 256                        // rows per chunk (one warp in A/C)
#define NCHK 391                       // 390*256 + 160 = 100000
#define GAB 49                         // ceil(391/8) blocks per batch (A, C)
#define SLICES 64                      // warp-slices per bucket in MAIN
#define GXM 128                        // MAIN blocks per batch (128*8 = 1024 = 16*64)
#define NBLKM (GXM * BB)               // 512
#define NE_REAL 528                    // 256 D | 256 INTER | 16 S1M
#define NE_TOT (BB * NE_REAL)

__device__ unsigned char g_vlab[BB][NN];
__device__ int g_hist[BB][NCHK][16];
__device__ int g_off[BB][NCHK][16];
__device__ int g_bcnt[BB][16];
__device__ float g_msort[BB][NN * 16];        // bucket-sorted valid mask rows
__device__ float g_sl[BB * 16 * SLICES][48];  // per-slice: 16 D | 16 B | 16 I
__device__ int g_count;                       // self-resetting

// ---------------------------------------------------------------------------
// Phase A: labels (valid-folded) + per-chunk histograms. Streaming shape.
// ---------------------------------------------------------------------------
__global__ void __launch_bounds__(256) phaseA_kernel(
    const float* __restrict__ gt, const float* __restrict__ valid) {
    const int b = blockIdx.y;
    const int t = threadIdx.x, lane = t & 31, w = t >> 5;
    const int c = blockIdx.x * 8 + w;
    __shared__ int hist_s[8][16];
    if (lane < 16) hist_s[w][lane] = 0;
    if (c >= NCHK) return;

    const float* gt_b = gt + (size_t)b * NN * KK;
    const float* v_b = valid + (size_t)b * NN;
    const int c0 = c * CHK;
    const int nrows = (c == NCHK - 1) ? (NN - c0) : CHK;
    const int iters = nrows >> 5;
    const unsigned FULL = 0xffffffffu;

    for (int it = 0; it < iters; it++) {
        const int base = c0 + it * 32;
        const float* src = gt_b + (size_t)base * KK;
        float vv[16];
#pragma unroll
        for (int s = 0; s < 16; s++) vv[s] = __ldg(src + s * 32 + lane);
        float myv = __ldg(v_b + base + lane);

        int mylab = 255;
#pragma unroll
        for (int s = 0; s < 16; s++) {
            unsigned bal = __ballot_sync(FULL, vv[s] > 0.5f);
            int l0 = __ffs(bal & 0xffffu) - 1;
            int l1 = __ffs(bal >> 16) - 1;
            if ((lane >> 1) == s) mylab = (lane & 1) ? l1 : l0;
        }
        if (myv <= 0.5f) mylab = 255;
        g_vlab[b][base + lane] = (unsigned char)mylab;

        unsigned mg = __match_any_sync(FULL, mylab);
        if (mylab < 16) {
            int leader = __ffs(mg) - 1;
            if (lane == leader) hist_s[w][mylab] += __popc(mg);
        }
    }
    __syncwarp();
    if (lane < 16) g_hist[b][c][lane] = hist_s[w][lane];
}

// ---------------------------------------------------------------------------
// Phase B: parallel within-bucket scans. One block per (b, j), 512 threads.
// ---------------------------------------------------------------------------
__global__ void __launch_bounds__(512) phaseB_kernel() {
    const int b = blockIdx.x >> 4, j = blockIdx.x & 15;
    const int t = threadIdx.x;
    __shared__ int sc[512];
    int o = (t < NCHK) ? g_hist[b][t][j] : 0;
    sc[t] = o;
    __syncthreads();
    for (int off = 1; off < 512; off <<= 1) {
        int v = (t >= off) ? sc[t - off] : 0;
        __syncthreads();
        sc[t] += v;
        __syncthreads();
    }
    if (t < NCHK) g_off[b][t][j] = sc[t] - o;
    if (t == NCHK - 1) g_bcnt[b][j] = sc[t];
}

// ---------------------------------------------------------------------------
// Phase C: scatter mask rows into bucket-sorted g_msort.
// ---------------------------------------------------------------------------
__global__ void __launch_bounds__(256) phaseC_kernel(
    const float* __restrict__ mask) {
    const int b = blockIdx.y;
    const int t = threadIdx.x, lane = t & 31, w = t >> 5;
    const int c = blockIdx.x * 8 + w;
    __shared__ int off_s[8][16];
    if (c >= NCHK) return;
    const unsigned FULL = 0xffffffffu;

    {
        int cnt = (lane < 16) ? g_bcnt[b][lane] : 0;
        int inc = cnt;
#pragma unroll
        for (int d = 1; d < 16; d <<= 1) {
            int v = __shfl_up_sync(FULL, inc, d);
            if (lane >= d && lane < 16) inc += v;
        }
        if (lane < 16) off_s[w][lane] = g_off[b][c][lane] + (inc - cnt);
    }
    __syncwarp();

    const float* mask_b = mask + (size_t)b * NN * KK;
    float* dst_b = g_msort[b];
    const int c0 = c * CHK;
    const int nrows = (c == NCHK - 1) ? (NN - c0) : CHK;
    const int iters = nrows >> 5;
    const int i = lane & 15, rh = lane >> 4;

    for (int it = 0; it < iters; it++) {
        const int base = c0 + it * 32;
        const float* src = mask_b + (size_t)base * KK;
        float vv[16];
#pragma unroll
        for (int s = 0; s < 16; s++) vv[s] = __ldg(src + s * 32 + lane);

        int mylab = g_vlab[b][base + lane];
        unsigned mg = __match_any_sync(FULL, mylab);
        int idx = -1;
        if (mylab < 16) {
            int leader = __ffs(mg) - 1;
            int rank = __popc(mg & ((1u << lane) - 1));
            int bs = 0;
            if (lane == leader) {
                bs = off_s[w][mylab];
                off_s[w][mylab] = bs + __popc(mg);
            }
            bs = __shfl_sync(mg, bs, leader);
            idx = bs + rank;
        }
#pragma unroll
        for (int s = 0; s < 16; s++) {
            int d = __shfl_sync(FULL, idx, 2 * s + rh);
            if (d >= 0) dst_b[(size_t)d * 16 + i] = vv[s];
        }
    }
}

// ---------------------------------------------------------------------------
// MAIN: sequential product-accumulation with 4 INDEPENDENT accumulator
// chains (k = s2 & 3) -> dependent-latency per 32-row group drops ~5x.
// ---------------------------------------------------------------------------
__global__ void __launch_bounds__(256, 4) main_kernel(float* __restrict__ out) {
    __shared__ float facc[NE_TOT];
    __shared__ float tmpB[BB][16][16];
    __shared__ float cost[BB][KK][KK];
    __shared__ float mS1M[BB][KK], mSUMM[BB][KK], mSUMG[BB][KK], mV[BB];
    __shared__ int colmap[BB][KK];
    __shared__ float rce[BB * KK], rdice[BB * KK];
    __shared__ int is_last;

    const int b = blockIdx.y, bx = blockIdx.x;
    const int t = threadIdx.x, lane = t & 31, w = t >> 5;
    const unsigned FULL = 0xffffffffu;
    const int gw = bx * 8 + w;          // [0, 1024)
    const int j = gw >> 6;              // bucket
    const int s = gw & 63;              // slice

    int cnt16 = (lane < 16) ? g_bcnt[b][lane] : 0;
    int inc = cnt16;
#pragma unroll
    for (int d = 1; d < 16; d <<= 1) {
        int v = __shfl_up_sync(FULL, inc, d);
        if (lane >= d && lane < 16) inc += v;
    }
    const int cj = __shfl_sync(FULL, cnt16, j);
    const int bbase = __shfl_sync(FULL, inc, j) - cj;
    const int chunk = (cj + SLICES - 1) / SLICES;
    int lo = s * chunk; if (lo > cj) lo = cj;
    int hi = lo + chunk; if (hi > cj) hi = cj;

    const float* src = g_msort[b] + (size_t)(bbase + lo) * 16;
    const int nrows = hi - lo;
    const int rh = lane >> 4;

    float Pm[4] = {1.0f, 1.0f, 1.0f, 1.0f};
    float P1[4] = {1.0f, 1.0f, 1.0f, 1.0f};
    int Em[4] = {0, 0, 0, 0}, E1[4] = {0, 0, 0, 0};
    float I = 0.0f;

#define RENORM1(kk)                                                          \
    do {                                                                     \
        int bm = __float_as_int(Pm[kk]);                                     \
        Em[kk] += (bm >> 23) - 127;                                          \
        Pm[kk] = __int_as_float((bm & 0x7fffff) | 0x3f800000);               \
        int b1 = __float_as_int(P1[kk]);                                     \
        E1[kk] += (b1 >> 23) - 127;                                          \
        P1[kk] = __int_as_float((b1 & 0x7fffff) | 0x3f800000);               \
    } while (0)

    int g = 0;
    for (; g + 32 <= nrows; g += 32) {
        float vv[16];
#pragma unroll
        for (int s2 = 0; s2 < 16; s2++)
            vv[s2] = __ldg(src + (size_t)g * 16 + s2 * 32 + lane);
#pragma unroll
        for (int s2 = 0; s2 < 16; s2++) {
            float m = vv[s2];
            const int k = s2 & 3;
            Pm[k] *= m; P1[k] *= (1.0f - m); I += m;
        }
        RENORM1(0); RENORM1(1); RENORM1(2); RENORM1(3);
    }
    if (g < nrows) {
        const int rem = nrows - g;
#pragma unroll
        for (int s2 = 0; s2 < 16; s2++) {
            int r2 = 2 * s2 + rh;
            int ok = (r2 < rem);
            float m = ok ? __ldg(src + (size_t)g * 16 + s2 * 32 + lane) : 0.5f;
            float fm = ok ? m : 1.0f;
            float f1 = ok ? (1.0f - m) : 1.0f;
            const int k = s2 & 3;
            Pm[k] *= fm; P1[k] *= f1; I += ok ? m : 0.0f;
            if ((s2 & 3) == 3) { RENORM1(0); RENORM1(1); RENORM1(2); RENORM1(3); }
        }
        RENORM1(0); RENORM1(1); RENORM1(2); RENORM1(3);
    }

    // fold 4 accumulators (mantissas in [1,2): product of 4 < 16, safe)
    float PmT = (Pm[0] * Pm[1]) * (Pm[2] * Pm[3]);
    float P1T = (P1[0] * P1[1]) * (P1[2] * P1[3]);
    int EmT = Em[0] + Em[1] + Em[2] + Em[3];
    int E1T = E1[0] + E1[1] + E1[2] + E1[3];

    // combine rh halves
    PmT *= __shfl_xor_sync(FULL, PmT, 16);
    EmT += __shfl_xor_sync(FULL, EmT, 16);
    P1T *= __shfl_xor_sync(FULL, P1T, 16);
    E1T += __shfl_xor_sync(FULL, E1T, 16);
    I += __shfl_xor_sync(FULL, I, 16);

    float logm = (float)EmT + __log2f(PmT);
    float log1 = (float)E1T + __log2f(P1T);
    float* slot = g_sl[(b * 16 + j) * SLICES + s];
    if (lane < 16) {
        slot[lane] = log1 - logm;   // D slice
        slot[16 + lane] = log1;     // B slice (for S1M)
        slot[32 + lane] = I;        // INTER slice
    }

    __threadfence();
    __syncthreads();
    if (t == 0) {
        int old = atomicAdd(&g_count, 1);
        is_last = (old == NBLKM - 1);
    }
    __syncthreads();
    if (!is_last) return;
    if (t == 0) g_count = 0;

    // ---- reduce slices: 3072 outputs = 12 per thread ----
    {
        float acc[12];
#pragma unroll
        for (int k = 0; k < 12; k++) acc[k] = 0.0f;
        for (int ss = 0; ss < SLICES; ss++) {
#pragma unroll
            for (int k = 0; k < 12; k++) {
                int q = t + k * 256;
                int kind = q >> 10;
                int sub = q & 1023;
                int bb2 = sub >> 8;
                int jj = (sub >> 4) & 15;
                int ii = sub & 15;
                acc[k] += g_sl[(bb2 * 16 + jj) * SLICES + ss][kind * 16 + ii];
            }
        }
#pragma unroll
        for (int k = 0; k < 12; k++) {
            int q = t + k * 256;
            int kind = q >> 10;
            int sub = q & 1023;
            int bb2 = sub >> 8;
            int jj = (sub >> 4) & 15;
            int ii = sub & 15;
            if (kind == 0) facc[bb2 * NE_REAL + ii * 16 + jj] = acc[k];
            else if (kind == 2) facc[bb2 * NE_REAL + 256 + ii * 16 + jj] = acc[k];
            else tmpB[bb2][jj][ii] = acc[k];
        }
    }
    __syncthreads();
    if (t < 64) {
        int bb2 = t >> 4, ii = t & 15;
        float sm = 0.0f;
#pragma unroll
        for (int jj = 0; jj < 16; jj++) sm += tmpB[bb2][jj][ii];
        facc[bb2 * NE_REAL + 512 + ii] = -sm;   // S1M
    }
    __syncthreads();

    // ---- marginals ----
    if (t < BB * KK) {
        int bb2 = t / KK, q = t % KK;
        const float* F = facc + bb2 * NE_REAL;
        float summ = 0.0f, sumg = 0.0f;
#pragma unroll
        for (int x = 0; x < KK; x++) {
            summ += F[256 + q * 16 + x];
            sumg += F[256 + x * 16 + q];
        }
        mS1M[bb2][q] = F[512 + q];
        mSUMM[bb2][q] = summ;
        mSUMG[bb2][q] = sumg;
    }
    __syncthreads();
    if (t < BB) {
        float v = 0.0f;
#pragma unroll
        for (int x = 0; x < KK; x++) v += (float)g_bcnt[t][x];
        mV[t] = v;
    }
    __syncthreads();

    // ---- cost matrices ----
    const float LN2 = 0.69314718055994530942f;
    for (int idx = t; idx < BB * 256; idx += 256) {
        int bb2 = idx >> 8;
        int r = idx & 255;
        int ii = r >> 4, jj = r & 15;
        const float* F = facc + bb2 * NE_REAL;
        float denom = fmaxf(mV[bb2], 1.0f);
        float ce = LN2 * (F[ii * 16 + jj] + mS1M[bb2][ii]) / denom;
        float dice = 1.0f - 2.0f * F[256 + ii * 16 + jj] /
                                (mSUMM[bb2][ii] + mSUMG[bb2][jj] + EPSF);
        cost[bb2][ii][jj] = W_CE * ce + W_DICE * dice;
    }
    __syncthreads();

    // ---- warp-parallel Hungarian (JV), one warp per batch ----
    if (w < BB) {
        const int bb2 = w;
        float ur = 0.0f, vv = 0.0f;
        int pcol = 0;
        for (int ii = 1; ii <= KK; ii++) {
            if (lane == 0) pcol = ii;
            float minv = 1e30f;
            int way = 0, used = 0, rowcov = 0, j0 = 0;
            while (true) {
                if (lane == j0) used = 1;
                int i0 = __shfl_sync(FULL, pcol, j0);
                if (lane == i0) rowcov = 1;
                float u_i0 = __shfl_sync(FULL, ur, i0);
                int active = (lane >= 1 && lane <= KK && !used);
                if (active) {
                    float c2 = cost[bb2][i0 - 1][lane - 1];
                    float cur = c2 - u_i0 - vv;
                    if (cur < minv) { minv = cur; way = j0; }
                }
                float val = active ? minv : 1e30f;
                float red = val;
#pragma unroll
                for (int off = 16; off; off >>= 1)
                    red = fminf(red, __shfl_xor_sync(FULL, red, off));
                unsigned bal = __ballot_sync(FULL, val == red);
                int j1 = __ffs(bal) - 1;
                float delta = red;
                if (rowcov) ur += delta;
                if (used) vv -= delta;
                else if (lane >= 1 && lane <= KK) minv -= delta;
                j0 = j1;
                int pj = __shfl_sync(FULL, pcol, j0);
                if (pj == 0) break;
            }
            while (j0 != 0) {
                int j1 = __shfl_sync(FULL, way, j0);
                int pv = __shfl_sync(FULL, pcol, j1);
                if (lane == j0) pcol = pv;
                j0 = j1;
            }
        }
        if (lane >= 1 && lane <= KK) colmap[bb2][pcol - 1] = lane - 1;
    }
    __syncthreads();

    // ---- loss ----
    if (t < BB * KK) {
        int bb2 = t / KK, ii = t % KK;
        int jj = colmap[bb2][ii];
        const float* F = facc + bb2 * NE_REAL;
        rce[t] = LN2 * (F[ii * 16 + jj] + mS1M[bb2][ii]);
        rdice[t] = 1.0f - 2.0f * F[256 + ii * 16 + jj] /
                              (mSUMM[bb2][ii] + mSUMG[bb2][jj] + EPSF);
    }
    __syncthreads();

    if (t == 0) {
        float cs = 0.0f, ds = 0.0f, vt = 0.0f;
        for (int x = 0; x < BB * KK; x++) { cs += rce[x]; ds += rdice[x]; }
        for (int bb2 = 0; bb2 < BB; bb2++) vt += mV[bb2];
        float l_ce = cs / (fmaxf(vt, 1.0f) * (float)KK);
        float l_dice = ds / (float)(BB * KK);
        out[0] = W_CE * l_ce + W_DICE * l_dice;
    }
}

// ---------------------------------------------------------------------------
extern "C" void kernel_launch(void* const* d_in, const int* in_sizes, int n_in,
                              void* d_out, int out_size) {
    const float* mask = (const float*)d_in[0];
    const float* gt = (const float*)d_in[1];
    const float* valid = (const float*)d_in[2];
    float* out = (float*)d_out;

    dim3 gA(GAB, BB);
    phaseA_kernel<<<gA, 256>>>(gt, valid);
    phaseB_kernel<<<64, 512>>>();
    phaseC_kernel<<<gA, 256>>>(mask);
    dim3 gM(GXM, BB);
    main_kernel<<<gM, 256>>>(out);
}

// round 17
// speedup vs baseline: 2.3870x; 1.1374x over previous
#include <cuda_runtime.h>
#include <math.h>
#include <stdint.h>

#define BB 4
#define NN 100000
#define KK 16
#define EPSF 1e-6f
#define W_CE 2.0f
#define W_DICE 0.1f

#define CHK 256                        // rows per chunk (one warp in A/C)
#define NCHK 391                       // 390*256 + 160 = 100000
#define GAB 49                         // ceil(391/8) blocks per batch (A, C)
#define SLICES 64                      // warp-slices per bucket in MAIN
#define SBLK 8                         // slice-blocks per bucket (8 warps each)
#define GXM (16 * SBLK)                // 128 MAIN blocks per batch
#define NE_REAL 528                    // 256 D | 256 INTER | 16 S1M
#define NE_TOT (BB * NE_REAL)

__device__ unsigned char g_vlab[BB][NN];
__device__ int g_hist[BB][NCHK][16];
__device__ int g_off[BB][NCHK][16];
__device__ int g_bcnt[BB][16];
__device__ float g_msort[BB][NN * 16];           // bucket-sorted valid mask rows
__device__ float g_sl2[BB * 16 * SBLK * 48];     // per-block partials: 16D|16B|16I

// ---------------------------------------------------------------------------
// Phase A: labels (valid-folded) + per-chunk histograms. Streaming shape.
// ---------------------------------------------------------------------------
__global__ void __launch_bounds__(256) phaseA_kernel(
    const float* __restrict__ gt, const float* __restrict__ valid) {
    const int b = blockIdx.y;
    const int t = threadIdx.x, lane = t & 31, w = t >> 5;
    const int c = blockIdx.x * 8 + w;
    __shared__ int hist_s[8][16];
    if (lane < 16) hist_s[w][lane] = 0;
    if (c >= NCHK) return;

    const float* gt_b = gt + (size_t)b * NN * KK;
    const float* v_b = valid + (size_t)b * NN;
    const int c0 = c * CHK;
    const int nrows = (c == NCHK - 1) ? (NN - c0) : CHK;
    const int iters = nrows >> 5;
    const unsigned FULL = 0xffffffffu;

    for (int it = 0; it < iters; it++) {
        const int base = c0 + it * 32;
        const float* src = gt_b + (size_t)base * KK;
        float vv[16];
#pragma unroll
        for (int s = 0; s < 16; s++) vv[s] = __ldg(src + s * 32 + lane);
        float myv = __ldg(v_b + base + lane);

        int mylab = 255;
#pragma unroll
        for (int s = 0; s < 16; s++) {
            unsigned bal = __ballot_sync(FULL, vv[s] > 0.5f);
            int l0 = __ffs(bal & 0xffffu) - 1;
            int l1 = __ffs(bal >> 16) - 1;
            if ((lane >> 1) == s) mylab = (lane & 1) ? l1 : l0;
        }
        if (myv <= 0.5f) mylab = 255;
        g_vlab[b][base + lane] = (unsigned char)mylab;

        unsigned mg = __match_any_sync(FULL, mylab);
        if (mylab < 16) {
            int leader = __ffs(mg) - 1;
            if (lane == leader) hist_s[w][mylab] += __popc(mg);
        }
    }
    __syncwarp();
    if (lane < 16) g_hist[b][c][lane] = hist_s[w][lane];
}

// ---------------------------------------------------------------------------
// Phase B: parallel within-bucket scans. One block per (b, j), 512 threads.
// ---------------------------------------------------------------------------
__global__ void __launch_bounds__(512) phaseB_kernel() {
    const int b = blockIdx.x >> 4, j = blockIdx.x & 15;
    const int t = threadIdx.x;
    __shared__ int sc[512];
    int o = (t < NCHK) ? g_hist[b][t][j] : 0;
    sc[t] = o;
    __syncthreads();
    for (int off = 1; off < 512; off <<= 1) {
        int v = (t >= off) ? sc[t - off] : 0;
        __syncthreads();
        sc[t] += v;
        __syncthreads();
    }
    if (t < NCHK) g_off[b][t][j] = sc[t] - o;
    if (t == NCHK - 1) g_bcnt[b][j] = sc[t];
}

// ---------------------------------------------------------------------------
// Phase C: scatter mask rows into bucket-sorted g_msort.
// ---------------------------------------------------------------------------
__global__ void __launch_bounds__(256) phaseC_kernel(
    const float* __restrict__ mask) {
    const int b = blockIdx.y;
    const int t = threadIdx.x, lane = t & 31, w = t >> 5;
    const int c = blockIdx.x * 8 + w;
    __shared__ int off_s[8][16];
    if (c >= NCHK) return;
    const unsigned FULL = 0xffffffffu;

    {
        int cnt = (lane < 16) ? g_bcnt[b][lane] : 0;
        int inc = cnt;
#pragma unroll
        for (int d = 1; d < 16; d <<= 1) {
            int v = __shfl_up_sync(FULL, inc, d);
            if (lane >= d && lane < 16) inc += v;
        }
        if (lane < 16) off_s[w][lane] = g_off[b][c][lane] + (inc - cnt);
    }
    __syncwarp();

    const float* mask_b = mask + (size_t)b * NN * KK;
    float* dst_b = g_msort[b];
    const int c0 = c * CHK;
    const int nrows = (c == NCHK - 1) ? (NN - c0) : CHK;
    const int iters = nrows >> 5;
    const int i = lane & 15, rh = lane >> 4;

    for (int it = 0; it < iters; it++) {
        const int base = c0 + it * 32;
        const float* src = mask_b + (size_t)base * KK;
        float vv[16];
#pragma unroll
        for (int s = 0; s < 16; s++) vv[s] = __ldg(src + s * 32 + lane);

        int mylab = g_vlab[b][base + lane];
        unsigned mg = __match_any_sync(FULL, mylab);
        int idx = -1;
        if (mylab < 16) {
            int leader = __ffs(mg) - 1;
            int rank = __popc(mg & ((1u << lane) - 1));
            int bs = 0;
            if (lane == leader) {
                bs = off_s[w][mylab];
                off_s[w][mylab] = bs + __popc(mg);
            }
            bs = __shfl_sync(mg, bs, leader);
            idx = bs + rank;
        }
#pragma unroll
        for (int s = 0; s < 16; s++) {
            int d = __shfl_sync(FULL, idx, 2 * s + rh);
            if (d >= 0) dst_b[(size_t)d * 16 + i] = vv[s];
        }
    }
}

// ---------------------------------------------------------------------------
// MAIN: product accumulation (4 independent chains) + in-block reduction of
// the 8 warp-slices -> ONE 48-float partial per block. No grid barrier.
// Block bx: bucket j = bx>>3, slice-block sblk = bx&7, warp slice = sblk*8+w.
// ---------------------------------------------------------------------------
__global__ void __launch_bounds__(256, 4) main_kernel() {
    __shared__ float red[8][48];

    const int b = blockIdx.y, bx = blockIdx.x;
    const int t = threadIdx.x, lane = t & 31, w = t >> 5;
    const unsigned FULL = 0xffffffffu;
    const int j = bx >> 3;
    const int sblk = bx & 7;
    const int s = sblk * 8 + w;         // slice in [0, 64)

    int cnt16 = (lane < 16) ? g_bcnt[b][lane] : 0;
    int inc = cnt16;
#pragma unroll
    for (int d = 1; d < 16; d <<= 1) {
        int v = __shfl_up_sync(FULL, inc, d);
        if (lane >= d && lane < 16) inc += v;
    }
    const int cj = __shfl_sync(FULL, cnt16, j);
    const int bbase = __shfl_sync(FULL, inc, j) - cj;
    const int chunk = (cj + SLICES - 1) / SLICES;
    int lo = s * chunk; if (lo > cj) lo = cj;
    int hi = lo + chunk; if (hi > cj) hi = cj;

    const float* src = g_msort[b] + (size_t)(bbase + lo) * 16;
    const int nrows = hi - lo;
    const int rh = lane >> 4;

    float Pm[4] = {1.0f, 1.0f, 1.0f, 1.0f};
    float P1[4] = {1.0f, 1.0f, 1.0f, 1.0f};
    int Em[4] = {0, 0, 0, 0}, E1[4] = {0, 0, 0, 0};
    float I = 0.0f;

#define RENORM1(kk)                                                          \
    do {                                                                     \
        int bm = __float_as_int(Pm[kk]);                                     \
        Em[kk] += (bm >> 23) - 127;                                          \
        Pm[kk] = __int_as_float((bm & 0x7fffff) | 0x3f800000);               \
        int b1 = __float_as_int(P1[kk]);                                     \
        E1[kk] += (b1 >> 23) - 127;                                          \
        P1[kk] = __int_as_float((b1 & 0x7fffff) | 0x3f800000);               \
    } while (0)

    int g = 0;
    for (; g + 32 <= nrows; g += 32) {
        float vv[16];
#pragma unroll
        for (int s2 = 0; s2 < 16; s2++)
            vv[s2] = __ldg(src + (size_t)g * 16 + s2 * 32 + lane);
#pragma unroll
        for (int s2 = 0; s2 < 16; s2++) {
            float m = vv[s2];
            const int k = s2 & 3;
            Pm[k] *= m; P1[k] *= (1.0f - m); I += m;
        }
        RENORM1(0); RENORM1(1); RENORM1(2); RENORM1(3);
    }
    if (g < nrows) {
        const int rem = nrows - g;
#pragma unroll
        for (int s2 = 0; s2 < 16; s2++) {
            int r2 = 2 * s2 + rh;
            int ok = (r2 < rem);
            float m = ok ? __ldg(src + (size_t)g * 16 + s2 * 32 + lane) : 0.5f;
            float fm = ok ? m : 1.0f;
            float f1 = ok ? (1.0f - m) : 1.0f;
            const int k = s2 & 3;
            Pm[k] *= fm; P1[k] *= f1; I += ok ? m : 0.0f;
            if ((s2 & 3) == 3) { RENORM1(0); RENORM1(1); RENORM1(2); RENORM1(3); }
        }
        RENORM1(0); RENORM1(1); RENORM1(2); RENORM1(3);
    }

    float PmT = (Pm[0] * Pm[1]) * (Pm[2] * Pm[3]);
    float P1T = (P1[0] * P1[1]) * (P1[2] * P1[3]);
    int EmT = Em[0] + Em[1] + Em[2] + Em[3];
    int E1T = E1[0] + E1[1] + E1[2] + E1[3];

    PmT *= __shfl_xor_sync(FULL, PmT, 16);
    EmT += __shfl_xor_sync(FULL, EmT, 16);
    P1T *= __shfl_xor_sync(FULL, P1T, 16);
    E1T += __shfl_xor_sync(FULL, E1T, 16);
    I += __shfl_xor_sync(FULL, I, 16);

    float logm = (float)EmT + __log2f(PmT);
    float log1 = (float)E1T + __log2f(P1T);
    if (lane < 16) {
        red[w][lane] = log1 - logm;   // D slice
        red[w][16 + lane] = log1;     // B slice
        red[w][32 + lane] = I;        // INTER slice
    }
    __syncthreads();

    // in-block reduce over 8 warps -> one partial per block
    if (t < 48) {
        float sm = 0.0f;
#pragma unroll
        for (int ww = 0; ww < 8; ww++) sm += red[ww][t];
        g_sl2[((b * 16 + j) * SBLK + sblk) * 48 + t] = sm;
    }
}

// ---------------------------------------------------------------------------
// FIN: reduce 8 partials per (b,j) -> cost -> Hungarian -> loss. One block.
// ---------------------------------------------------------------------------
__global__ void __launch_bounds__(256) fin_kernel(float* __restrict__ out) {
    __shared__ float facc[NE_TOT];
    __shared__ float tmpB[BB][16][16];
    __shared__ float cost[BB][KK][KK];
    __shared__ float mS1M[BB][KK], mSUMM[BB][KK], mSUMG[BB][KK], mV[BB];
    __shared__ int colmap[BB][KK];
    __shared__ float rce[BB * KK], rdice[BB * KK];

    const int t = threadIdx.x, lane = t & 31, w = t >> 5;
    const unsigned FULL = 0xffffffffu;

    // reduce: 3072 outputs = 12 per thread, 8 partials each
    {
#pragma unroll
        for (int k = 0; k < 12; k++) {
            int q = t + k * 256;
            int kind = q >> 10;                  // 0:D 1:B 2:I
            int sub = q & 1023;
            int bb2 = sub >> 8;
            int jj = (sub >> 4) & 15;
            int ii = sub & 15;
            const float* base =
                &g_sl2[((bb2 * 16 + jj) * SBLK) * 48 + kind * 16 + ii];
            float acc = 0.0f;
#pragma unroll
            for (int sb = 0; sb < SBLK; sb++) acc += base[sb * 48];
            if (kind == 0) facc[bb2 * NE_REAL + ii * 16 + jj] = acc;
            else if (kind == 2) facc[bb2 * NE_REAL + 256 + ii * 16 + jj] = acc;
            else tmpB[bb2][jj][ii] = acc;
        }
    }
    __syncthreads();
    if (t < 64) {
        int bb2 = t >> 4, ii = t & 15;
        float sm = 0.0f;
#pragma unroll
        for (int jj = 0; jj < 16; jj++) sm += tmpB[bb2][jj][ii];
        facc[bb2 * NE_REAL + 512 + ii] = -sm;   // S1M
    }
    __syncthreads();

    // marginals
    if (t < BB * KK) {
        int bb2 = t / KK, q = t % KK;
        const float* F = facc + bb2 * NE_REAL;
        float summ = 0.0f, sumg = 0.0f;
#pragma unroll
        for (int x = 0; x < KK; x++) {
            summ += F[256 + q * 16 + x];
            sumg += F[256 + x * 16 + q];
        }
        mS1M[bb2][q] = F[512 + q];
        mSUMM[bb2][q] = summ;
        mSUMG[bb2][q] = sumg;
    }
    __syncthreads();
    if (t < BB) {
        float v = 0.0f;
#pragma unroll
        for (int x = 0; x < KK; x++) v += (float)g_bcnt[t][x];
        mV[t] = v;
    }
    __syncthreads();

    // cost matrices
    const float LN2 = 0.69314718055994530942f;
    for (int idx = t; idx < BB * 256; idx += 256) {
        int bb2 = idx >> 8;
        int r = idx & 255;
        int ii = r >> 4, jj = r & 15;
        const float* F = facc + bb2 * NE_REAL;
        float denom = fmaxf(mV[bb2], 1.0f);
        float ce = LN2 * (F[ii * 16 + jj] + mS1M[bb2][ii]) / denom;
        float dice = 1.0f - 2.0f * F[256 + ii * 16 + jj] /
                                (mSUMM[bb2][ii] + mSUMG[bb2][jj] + EPSF);
        cost[bb2][ii][jj] = W_CE * ce + W_DICE * dice;
    }
    __syncthreads();

    // warp-parallel Hungarian (JV), one warp per batch
    if (w < BB) {
        const int bb2 = w;
        float ur = 0.0f, vv = 0.0f;
        int pcol = 0;
        for (int ii = 1; ii <= KK; ii++) {
            if (lane == 0) pcol = ii;
            float minv = 1e30f;
            int way = 0, used = 0, rowcov = 0, j0 = 0;
            while (true) {
                if (lane == j0) used = 1;
                int i0 = __shfl_sync(FULL, pcol, j0);
                if (lane == i0) rowcov = 1;
                float u_i0 = __shfl_sync(FULL, ur, i0);
                int active = (lane >= 1 && lane <= KK && !used);
                if (active) {
                    float c2 = cost[bb2][i0 - 1][lane - 1];
                    float cur = c2 - u_i0 - vv;
                    if (cur < minv) { minv = cur; way = j0; }
                }
                float val = active ? minv : 1e30f;
                float red2 = val;
#pragma unroll
                for (int off = 16; off; off >>= 1)
                    red2 = fminf(red2, __shfl_xor_sync(FULL, red2, off));
                unsigned bal = __ballot_sync(FULL, val == red2);
                int j1 = __ffs(bal) - 1;
                float delta = red2;
                if (rowcov) ur += delta;
                if (used) vv -= delta;
                else if (lane >= 1 && lane <= KK) minv -= delta;
                j0 = j1;
                int pj = __shfl_sync(FULL, pcol, j0);
                if (pj == 0) break;
            }
            while (j0 != 0) {
                int j1 = __shfl_sync(FULL, way, j0);
                int pv = __shfl_sync(FULL, pcol, j1);
                if (lane == j0) pcol = pv;
                j0 = j1;
            }
        }
        if (lane >= 1 && lane <= KK) colmap[bb2][pcol - 1] = lane - 1;
    }
    __syncthreads();

    // loss
    if (t < BB * KK) {
        int bb2 = t / KK, ii = t % KK;
        int jj = colmap[bb2][ii];
        const float* F = facc + bb2 * NE_REAL;
        rce[t] = LN2 * (F[ii * 16 + jj] + mS1M[bb2][ii]);
        rdice[t] = 1.0f - 2.0f * F[256 + ii * 16 + jj] /
                              (mSUMM[bb2][ii] + mSUMG[bb2][jj] + EPSF);
    }
    __syncthreads();

    if (t == 0) {
        float cs = 0.0f, ds = 0.0f, vt = 0.0f;
        for (int x = 0; x < BB * KK; x++) { cs += rce[x]; ds += rdice[x]; }
        for (int bb2 = 0; bb2 < BB; bb2++) vt += mV[bb2];
        float l_ce = cs / (fmaxf(vt, 1.0f) * (float)KK);
        float l_dice = ds / (float)(BB * KK);
        out[0] = W_CE * l_ce + W_DICE * l_dice;
    }
}

// ---------------------------------------------------------------------------
extern "C" void kernel_launch(void* const* d_in, const int* in_sizes, int n_in,
                              void* d_out, int out_size) {
    const float* mask = (const float*)d_in[0];
    const float* gt = (const float*)d_in[1];
    const float* valid = (const float*)d_in[2];
    float* out = (float*)d_out;

    dim3 gA(GAB, BB);
    phaseA_kernel<<<gA, 256>>>(gt, valid);
    phaseB_kernel<<<64, 512>>>();
    phaseC_kernel<<<gA, 256>>>(mask);
    dim3 gM(GXM, BB);
    main_kernel<<<gM, 256>>>();
    fin_kernel<<<1, 256>>>(out);
}